// round 12
// baseline (speedup 1.0000x reference)
#include <cuda_runtime.h>
#include <cstdint>

// GlobalWorkspace: exact EMA scan + per-step threshold/top-2 + mask rows.
//
//   K2' k_packscan : 128 blocks x 256 thr. Warps 1-7 stream spikes rows
//                    (coalesced 128B/row slice) -> ballot -> smem bit column,
//                    pipelined in 8x1024-step segments against warp 0's
//                    bit-exact serial EMA scan. Emits 32-step carries,
//                    nmda_final, and the packed bit column (for K3).
//   K3  k_topk     : per 32-step chunk: replay EMA from exact carry with the
//                    512KB row zero-stores interleaved into the step loop,
//                    REDUX-based exact top-2 (score bits + ~idx tie-break) +
//                    raw max; coverage + two 1.0 scatters per ignited row.
//
// XLA contracts (0.99*v + 0.01*s) into fma(0.99, v, 0.01*s); 0.01*s is exact
// for s in {0,1}. __fmaf_rn replicates it so all discrete decisions bit-match.

#define EMA_MUL 0.99f
#define EMA_ADD 0.01f
#define WTA     0.85f
#define THR     0.58f

#define MAX_T 8192
#define MAX_N 4096
#define CHUNK 32
#define SEG   1024

// scratch (static __device__ — no allocations allowed)
static __device__ unsigned g_bitsT[(size_t)(MAX_N / 32) * MAX_T];         // 4 MiB, [word][t]
static __device__ float    g_carry[(size_t)(MAX_T / CHUNK) * MAX_N];      // 4 MiB

// ---------------------------------------------------------------- K2'
// grid = N/32 blocks x 256 threads. Block b owns neurons b*32..b*32+31.
__global__ __launch_bounds__(256) void k_packscan(const float* __restrict__ spikes,
                                                  const float* __restrict__ nmda0,
                                                  float* __restrict__ nmda_final,
                                                  int T, int N)
{
    __shared__ unsigned scol[MAX_T];                 // 32 KB bit column
    const int tid  = threadIdx.x;
    const int w    = tid >> 5;
    const int lane = tid & 31;
    const int b    = blockIdx.x;
    const int nseg = T / SEG;                        // 8

    // scan state (live only in warp 0)
    const int n = b * 32 + lane;
    const unsigned bitm = 1u << lane;
    float v = (w == 0) ? nmda0[n] : 0.0f;
    unsigned wa[CHUNK], wb[CHUNK];

    const float* col = spikes + (size_t)b * 32 + lane;   // + t*N per step

    for (int stage = 0; stage <= nseg; stage++) {
        // ---- producers: warps 1..7 fill segment `stage`
        if (stage < nseg && w > 0) {
            const int segend = (stage + 1) * SEG;
            int t = stage * SEG + (w - 1);
            // unrolled-by-8 main loop (8 outstanding loads per warp)
            for (; t + 7 * 7 < segend; t += 7 * 8) {
                float f[8];
                #pragma unroll
                for (int j = 0; j < 8; j++) f[j] = col[(size_t)(t + 7 * j) * N];
                #pragma unroll
                for (int j = 0; j < 8; j++) {
                    unsigned word = __ballot_sync(0xffffffffu, f[j] != 0.0f);
                    if (lane == 0) scol[t + 7 * j] = word;
                }
            }
            for (; t < segend; t += 7) {
                float f = col[(size_t)t * N];
                unsigned word = __ballot_sync(0xffffffffu, f != 0.0f);
                if (lane == 0) scol[t] = word;
            }
        }
        // ---- scan warp: consume segment `stage-1`
        if (stage > 0 && w == 0) {
            const int sb = (stage - 1) * SEG;        // segment base step
            const int cb = sb / CHUNK;               // segment base chunk
            #pragma unroll
            for (int i = 0; i < CHUNK; i++) wa[i] = scol[sb + i];
            for (int cc = 0; cc < SEG / CHUNK; cc += 2) {
                g_carry[(size_t)(cb + cc) * N + n] = v;
                #pragma unroll
                for (int i = 0; i < CHUNK; i++) wb[i] = scol[sb + (cc + 1) * CHUNK + i];
                #pragma unroll
                for (int i = 0; i < CHUNK; i++) {
                    float a = (wa[i] & bitm) ? EMA_ADD : 0.0f;
                    v = __fmaf_rn(EMA_MUL, v, a);
                }
                g_carry[(size_t)(cb + cc + 1) * N + n] = v;
                if (cc + 2 < SEG / CHUNK) {
                    #pragma unroll
                    for (int i = 0; i < CHUNK; i++) wa[i] = scol[sb + (cc + 2) * CHUNK + i];
                }
                #pragma unroll
                for (int i = 0; i < CHUNK; i++) {
                    float a = (wb[i] & bitm) ? EMA_ADD : 0.0f;
                    v = __fmaf_rn(EMA_MUL, v, a);
                }
            }
        }
        __syncthreads();
    }

    if (w == 0) nmda_final[n] = v;

    // bulk-copy the packed bit column to global for K3 (coalesced uint4)
    {
        uint4* dst = (uint4*)(g_bitsT + (size_t)b * T);
        const uint4* src = (const uint4*)scol;
        for (int i = tid; i < T / 4; i += 256) dst[i] = src[i];
    }
}

// ---------------------------------------------------------------- K3
__device__ __forceinline__ void top2_merge(unsigned long long& m1, unsigned long long& m2,
                                           unsigned long long o1, unsigned long long o2)
{
    bool g = m1 > o1;
    unsigned long long hi = g ? m1 : o1;
    unsigned long long lo = g ? o1 : m1;
    unsigned long long s2 = (m2 > o2) ? m2 : o2;
    m1 = hi;
    m2 = (lo > s2) ? lo : s2;
}

// 256 threads, 16 neurons/thread (N=4096). blockIdx = chunk (32 steps).
__global__ __launch_bounds__(256) void k_topk(float* __restrict__ out_mask,
                                              float* __restrict__ out_cov,
                                              int N, int T)
{
    __shared__ unsigned sbits[128 * 33];             // padded [wq][t] tile
    __shared__ unsigned long long sm1[CHUNK * 8];
    __shared__ unsigned long long sm2[CHUNK * 8];
    __shared__ float smax[CHUNK * 8];
    __shared__ unsigned sidx[CHUNK * 2];

    const int tid = threadIdx.x;
    const int c   = blockIdx.x;
    const int w   = tid >> 5, lane = tid & 31;
    const int NW  = N >> 5;                          // 128

    // load bit tile from transposed layout (coalesced: warp = one column seg)
    for (int j = tid; j < NW * CHUNK; j += 256) {
        int wq = j >> 5, tt = j & 31;
        sbits[wq * 33 + tt] = g_bitsT[(size_t)wq * T + c * CHUNK + tt];
    }

    // load exact carry for my 16 neurons
    const int base = tid * 16;
    float ema[16];
    {
        const float4* cr = (const float4*)(g_carry + (size_t)c * N + base);
        #pragma unroll
        for (int q = 0; q < 4; q++) {
            float4 f = cr[q];
            ema[q * 4 + 0] = f.x; ema[q * 4 + 1] = f.y;
            ema[q * 4 + 2] = f.z; ema[q * 4 + 3] = f.w;
        }
    }
    __syncthreads();

    float4* out4 = (float4*)(out_mask + (size_t)c * CHUNK * N);
    const float4 zf4 = make_float4(0.f, 0.f, 0.f, 0.f);
    const unsigned invb = ~(unsigned)base;           // ~(base+j) = invb - j

    // ---- phase A: replay 32 steps, zero-stores interleaved with compute
    for (int t = 0; t < CHUNK; t++) {
        // D1 slice: 1024 float4 zeros per step (this block's region)
        {
            int zb = t * 1024 + tid;
            out4[zb] = zf4; out4[zb + 256] = zf4;
            out4[zb + 512] = zf4; out4[zb + 768] = zf4;
        }

        unsigned word = sbits[(tid >> 1) * 33 + t];
        unsigned half = word >> ((tid & 1) << 4);

        unsigned b1 = 0u, i1 = 0xffffffffu, b2 = 0u, i2 = 0xffffffffu;
        float rloc = 0.0f;
        #pragma unroll
        for (int j = 0; j < 16; j++) {
            float a = ((half >> j) & 1u) ? EMA_ADD : 0.0f;
            float e = __fmaf_rn(EMA_MUL, ema[j], a); // identical to K2's update
            ema[j] = e;
            rloc = fmaxf(rloc, e);
            unsigned sb = __float_as_uint(__fmul_rn(e, WTA));
            unsigned iv = invb - j;
            bool p1 = sb > b1;
            bool p2 = sb > b2;
            b2 = p1 ? b1 : (p2 ? sb : b2);
            i2 = p1 ? i1 : (p2 ? iv : i2);
            b1 = p1 ? sb : b1;
            i1 = p1 ? iv : i1;
        }
        unsigned rbits = __reduce_max_sync(0xffffffffu, __float_as_uint(rloc));

        // warp top-2 via REDUX: max score, owner (largest ~idx on ties),
        // then max over candidates with the owner's entry swapped for its 2nd.
        unsigned M1 = __reduce_max_sync(0xffffffffu, b1);
        unsigned I1 = __reduce_max_sync(0xffffffffu, (b1 == M1) ? i1 : 0u);
        bool own = (b1 == M1) && (i1 == I1);
        unsigned cb = own ? b2 : b1;
        unsigned ci = own ? i2 : i1;
        unsigned M2 = __reduce_max_sync(0xffffffffu, cb);
        unsigned I2 = __reduce_max_sync(0xffffffffu, (cb == M2) ? ci : 0u);

        if (lane == 0) {
            sm1[t * 8 + w] = ((unsigned long long)M1 << 32) | I1;
            sm2[t * 8 + w] = ((unsigned long long)M2 << 32) | I2;
            smax[t * 8 + w] = __uint_as_float(rbits);
        }
    }
    __syncthreads();

    // ---- phase B: cross-warp reduce (8 entries per step), finalize per step
    const float covval = __fdiv_rn(2.0f, (float)N);
    for (int t = w; t < CHUNK; t += 8) {
        unsigned long long m1 = 0ull, m2 = 0ull;
        float rmx = 0.0f;
        if (lane < 8) { m1 = sm1[t * 8 + lane]; m2 = sm2[t * 8 + lane]; rmx = smax[t * 8 + lane]; }
        #pragma unroll
        for (int d = 4; d >= 1; d >>= 1) {
            unsigned long long o1 = __shfl_xor_sync(0xffffffffu, m1, d);
            unsigned long long o2 = __shfl_xor_sync(0xffffffffu, m2, d);
            float om            = __shfl_xor_sync(0xffffffffu, rmx, d);
            top2_merge(m1, m2, o1, o2);
            rmx = fmaxf(rmx, om);
        }
        if (lane == 0) {
            bool ign = (rmx >= THR);
            out_cov[c * CHUNK + t] = ign ? covval : 0.0f;
            sidx[t * 2 + 0] = ign ? ~(unsigned)(m1 & 0xffffffffull) : 0xffffffffu;
            sidx[t * 2 + 1] = ign ? ~(unsigned)(m2 & 0xffffffffull) : 0xffffffffu;
        }
    }
    __syncthreads();   // orders D1 zero-stores + sidx before D2 ones

    // ---- D2: scatter the two ones per ignited row
    if (tid < CHUNK) {
        unsigned i1s = sidx[tid * 2 + 0];
        if (i1s != 0xffffffffu) {
            unsigned i2s = sidx[tid * 2 + 1];
            size_t ro = (size_t)(c * CHUNK + tid) * (size_t)N;
            out_mask[ro + i1s] = 1.0f;
            out_mask[ro + i2s] = 1.0f;
        }
    }
}

// ---------------------------------------------------------------- launch
extern "C" void kernel_launch(void* const* d_in, const int* in_sizes, int n_in,
                              void* d_out, int out_size)
{
    const float* spikes = (const float*)d_in[0];
    const float* nmda0  = (const float*)d_in[1];
    int N = in_sizes[1];
    long long total = in_sizes[0];
    int T = (int)(total / N);

    float* out      = (float*)d_out;
    float* out_cov  = out + (size_t)T * N;
    float* out_nmda = out_cov + T;

    k_packscan<<<N / 32, 256>>>(spikes, nmda0, out_nmda, T, N);
    k_topk<<<T / CHUNK, 256>>>(out, out_cov, N, T);
}